// round 10
// baseline (speedup 1.0000x reference)
#include <cuda_runtime.h>
#include <math.h>

#define BATCH    16384
#define MAZE_LEN 3844
#define NWARPS   4096          // each warp does rows w, w+4096, w+8192, w+12288

// 120 needed columns per row (3721 double-counted), all reciprocal-summed:
//   -log(clip(prod, e^-90)) == min(log(S - 127), 90)
// (S includes 8 dummy 1.0-reciprocals from inactive mid lanes per row.)
//
// DRAM-byte theory: wall sits at ~95% of DRAM spec for LINE-granular traffic
// (77 MB of 128B lines / 10.1us = 7.6 TB/s). Touched 32B SECTORS are only
// ~46 MB. __ldg (LDG.E.NC, texture path) appears to fetch whole lines; plain
// LDG.E requests sector fills. Drop .nc everywhere -> DRAM bytes should drop
// to the sector floor.

__device__ __forceinline__ float fast_rcp(float x) {
    float r;
    asm("rcp.approx.ftz.f32 %0, %1;" : "=f"(r) : "f"(x));
    return r;
}

// Fold 4 reciprocals into one MUFU.RCP.
__device__ __forceinline__ float fold4(float h, float t, float m0, float m1) {
    const float a   = h * t;
    const float b   = m0 * m1;
    const float num = (h + t) * b + (m0 + m1) * a;
    return num * fast_rcp(a * b);
}

__global__ __launch_bounds__(256)
void fuzzy_chain_kernel(const float* __restrict__ maze, float* __restrict__ out)
{
    const int warp_local  = threadIdx.x >> 5;                 // 0..7
    const int warp_global = blockIdx.x * 8 + warp_local;
    const int lane        = threadIdx.x & 31;

    // ---- per-lane scalar indices (shared by all 4 rows) ------------------
    int h_i = 4 * lane + 1;
    if (lane == 0) h_i = 1;
    if (lane == 1) h_i = 6;

    int t_i = 3717 + 4 * lane;
    if (lane == 29) t_i = 3721;                   // duplicate 3721
    if (lane == 30) t_i = 3839;
    if (lane == 31) t_i = 3841;

    const int k     = lane >> 1;
    const int comp  = lane & 1;
    const int p1    = 16 + k;
    const bool act1 = (p1 < 28);
    const int m0_i  = 124 * k + 245 + 4 * comp;
    const int m1_i  = 124 * (act1 ? p1 : 27) + 245 + 4 * comp;

    const float* __restrict__ r0 = maze + (size_t)warp_global * MAZE_LEN;
    const float* __restrict__ r1 = r0 + (size_t)NWARPS * MAZE_LEN;
    const float* __restrict__ r2 = r1 + (size_t)NWARPS * MAZE_LEN;
    const float* __restrict__ r3 = r2 + (size_t)NWARPS * MAZE_LEN;

    // ---- front-batch all 16 scalar loads (plain LDG.E, sector fills) -----
    const float h0 = r0[h_i], t0 = r0[t_i], a0 = r0[m0_i], b0l = r0[m1_i];
    const float h1 = r1[h_i], t1 = r1[t_i], a1 = r1[m0_i], b1l = r1[m1_i];
    const float h2 = r2[h_i], t2 = r2[t_i], a2 = r2[m0_i], b2l = r2[m1_i];
    const float h3 = r3[h_i], t3 = r3[t_i], a3 = r3[m0_i], b3l = r3[m1_i];

    const float b0 = act1 ? b0l : 1.0f;           // dummy -> rcp(1)=1, in constant
    const float b1 = act1 ? b1l : 1.0f;
    const float b2 = act1 ? b2l : 1.0f;
    const float b3 = act1 ? b3l : 1.0f;

    float s0 = fold4(h0, t0, a0, b0);
    float s1 = fold4(h1, t1, a1, b1);
    float s2 = fold4(h2, t2, a2, b2);
    float s3 = fold4(h3, t3, a3, b3);

    // ---- warp reduction of all 4 rows' S ---------------------------------
    #pragma unroll
    for (int off = 16; off > 0; off >>= 1) {
        s0 += __shfl_xor_sync(0xffffffffu, s0, off);
        s1 += __shfl_xor_sync(0xffffffffu, s1, off);
        s2 += __shfl_xor_sync(0xffffffffu, s2, off);
        s3 += __shfl_xor_sync(0xffffffffu, s3, off);
    }

    __shared__ float warp_vals[8];
    if (lane == 0) {
        // x==0 -> inf -> fminf -> 90; two zeros -> NaN -> fminf -> 90 (matches clip).
        const float v0 = fminf(logf(s0 - 127.0f), 90.0f);
        const float v1 = fminf(logf(s1 - 127.0f), 90.0f);
        const float v2 = fminf(logf(s2 - 127.0f), 90.0f);
        const float v3 = fminf(logf(s3 - 127.0f), 90.0f);
        warp_vals[warp_local] = (v0 + v1) + (v2 + v3);
    }
    __syncthreads();

    if (threadIdx.x == 0) {
        float t = 0.0f;
        #pragma unroll
        for (int i = 0; i < 8; i++) t += warp_vals[i];
        atomicAdd(out, t * (1.0f / (float)BATCH));   // exact power-of-two scale
    }
}

extern "C" void kernel_launch(void* const* d_in, const int* in_sizes, int n_in,
                              void* d_out, int out_size)
{
    const float* maze = (const float*)d_in[0];
    float*       out  = (float*)d_out;

    cudaMemsetAsync(out, 0, sizeof(float), 0);

    const int blocks = NWARPS / 8;                  // 512 CTAs, 256 threads each
    fuzzy_chain_kernel<<<blocks, 256>>>(maze, out);
}

// round 11
// speedup vs baseline: 1.0597x; 1.0597x over previous
#include <cuda_runtime.h>
#include <math.h>

#define BATCH    16384
#define MAZE_LEN 3844
#define NWARPS   4096          // each warp does rows w, w+4096, w+8192, w+12288
#define GRID     512           // 256-thread CTAs, 8 warps each

// 120 needed columns per row (3721 double-counted), all reciprocal-summed:
//   -log(clip(prod, e^-90)) == min(log(S - 127), 90)
// (S includes 8 dummy 1.0-reciprocals from inactive mid lanes per row.)
//
// Established facts: DRAM traffic is 128B-line-granular (88 MB, measured
// invariant across load paths/policies); __ldg(.nc) is the faster L1 path.
// This round: single-node graph. No memset — blocks accumulate into a
// __device__ accumulator; the last block writes d_out and resets the
// accumulators, so every replay starts from identical state.

__device__ float    g_acc;     // zero at module load; self-restoring per launch
__device__ unsigned g_cnt;

__device__ __forceinline__ float fast_rcp(float x) {
    float r;
    asm("rcp.approx.ftz.f32 %0, %1;" : "=f"(r) : "f"(x));
    return r;
}

// Fold 4 reciprocals into one MUFU.RCP.
__device__ __forceinline__ float fold4(float h, float t, float m0, float m1) {
    const float a   = h * t;
    const float b   = m0 * m1;
    const float num = (h + t) * b + (m0 + m1) * a;
    return num * fast_rcp(a * b);
}

__global__ __launch_bounds__(256)
void fuzzy_chain_kernel(const float* __restrict__ maze, float* __restrict__ out)
{
    const int warp_local  = threadIdx.x >> 5;                 // 0..7
    const int warp_global = blockIdx.x * 8 + warp_local;
    const int lane        = threadIdx.x & 31;

    // ---- per-lane scalar indices (shared by all 4 rows) ------------------
    int h_i = 4 * lane + 1;
    if (lane == 0) h_i = 1;
    if (lane == 1) h_i = 6;

    int t_i = 3717 + 4 * lane;
    if (lane == 29) t_i = 3721;                   // duplicate 3721
    if (lane == 30) t_i = 3839;
    if (lane == 31) t_i = 3841;

    const int k     = lane >> 1;
    const int comp  = lane & 1;
    const int p1    = 16 + k;
    const bool act1 = (p1 < 28);
    const int m0_i  = 124 * k + 245 + 4 * comp;
    const int m1_i  = 124 * (act1 ? p1 : 27) + 245 + 4 * comp;

    const float* __restrict__ r0 = maze + (size_t)warp_global * MAZE_LEN;
    const float* __restrict__ r1 = r0 + (size_t)NWARPS * MAZE_LEN;
    const float* __restrict__ r2 = r1 + (size_t)NWARPS * MAZE_LEN;
    const float* __restrict__ r3 = r2 + (size_t)NWARPS * MAZE_LEN;

    // ---- front-batch all 16 scalar loads (LDG.E.NC, best path) ----------
    const float h0 = __ldg(r0 + h_i), t0 = __ldg(r0 + t_i);
    const float a0 = __ldg(r0 + m0_i), b0l = __ldg(r0 + m1_i);
    const float h1 = __ldg(r1 + h_i), t1 = __ldg(r1 + t_i);
    const float a1 = __ldg(r1 + m0_i), b1l = __ldg(r1 + m1_i);
    const float h2 = __ldg(r2 + h_i), t2 = __ldg(r2 + t_i);
    const float a2 = __ldg(r2 + m0_i), b2l = __ldg(r2 + m1_i);
    const float h3 = __ldg(r3 + h_i), t3 = __ldg(r3 + t_i);
    const float a3 = __ldg(r3 + m0_i), b3l = __ldg(r3 + m1_i);

    const float b0 = act1 ? b0l : 1.0f;           // dummy -> rcp(1)=1, in constant
    const float b1 = act1 ? b1l : 1.0f;
    const float b2 = act1 ? b2l : 1.0f;
    const float b3 = act1 ? b3l : 1.0f;

    float s0 = fold4(h0, t0, a0, b0);
    float s1 = fold4(h1, t1, a1, b1);
    float s2 = fold4(h2, t2, a2, b2);
    float s3 = fold4(h3, t3, a3, b3);

    // ---- warp reduction of all 4 rows' S ---------------------------------
    #pragma unroll
    for (int off = 16; off > 0; off >>= 1) {
        s0 += __shfl_xor_sync(0xffffffffu, s0, off);
        s1 += __shfl_xor_sync(0xffffffffu, s1, off);
        s2 += __shfl_xor_sync(0xffffffffu, s2, off);
        s3 += __shfl_xor_sync(0xffffffffu, s3, off);
    }

    __shared__ float warp_vals[8];
    if (lane == 0) {
        // x==0 -> inf -> fminf -> 90; two zeros -> NaN -> fminf -> 90 (matches clip).
        const float v0 = fminf(logf(s0 - 127.0f), 90.0f);
        const float v1 = fminf(logf(s1 - 127.0f), 90.0f);
        const float v2 = fminf(logf(s2 - 127.0f), 90.0f);
        const float v3 = fminf(logf(s3 - 127.0f), 90.0f);
        warp_vals[warp_local] = (v0 + v1) + (v2 + v3);
    }
    __syncthreads();

    if (threadIdx.x == 0) {
        float t = 0.0f;
        #pragma unroll
        for (int i = 0; i < 8; i++) t += warp_vals[i];
        atomicAdd(&g_acc, t);
        __threadfence();
        const unsigned old = atomicAdd(&g_cnt, 1u);
        if (old == GRID - 1u) {
            // Every block's g_acc add precedes its g_cnt add (fenced), so all
            // partials are visible here.
            const float total = atomicAdd(&g_acc, 0.0f);
            out[0] = total * (1.0f / (float)BATCH);   // exact power-of-two scale
            g_acc = 0.0f;                             // restore for next replay
            g_cnt = 0u;
        }
    }
}

extern "C" void kernel_launch(void* const* d_in, const int* in_sizes, int n_in,
                              void* d_out, int out_size)
{
    const float* maze = (const float*)d_in[0];
    float*       out  = (float*)d_out;
    fuzzy_chain_kernel<<<GRID, 256>>>(maze, out);   // single graph node
}

// round 12
// speedup vs baseline: 1.1059x; 1.0436x over previous
#include <cuda_runtime.h>
#include <math.h>

#define BATCH    16384
#define MAZE_LEN 3844
#define NWARPS   4096          // each warp does rows 4w, 4w+1, 4w+2, 4w+3

// 120 needed columns per row (3721 double-counted), all reciprocal-summed:
//   -log(clip(prod, e^-90)) == min(log(S - 127), 90)
// (S includes 8 dummy 1.0-reciprocals from inactive mid lanes per row.)
//
// Established: DRAM traffic fixed at ~88 MB (line-granular, invariant to load
// path / L2 policy); memset+kernel 2-node graph beats in-kernel finalize.
// This round: CONSECUTIVE rows per warp -> each warp's 16 requests cluster in
// a 61 KB window, global stream ~address-ordered -> DRAM row-buffer locality.

__device__ __forceinline__ float fast_rcp(float x) {
    float r;
    asm("rcp.approx.ftz.f32 %0, %1;" : "=f"(r) : "f"(x));
    return r;
}

// Fold 4 reciprocals into one MUFU.RCP.
__device__ __forceinline__ float fold4(float h, float t, float m0, float m1) {
    const float a   = h * t;
    const float b   = m0 * m1;
    const float num = (h + t) * b + (m0 + m1) * a;
    return num * fast_rcp(a * b);
}

__global__ __launch_bounds__(256)
void fuzzy_chain_kernel(const float* __restrict__ maze, float* __restrict__ out)
{
    const int warp_local  = threadIdx.x >> 5;                 // 0..7
    const int warp_global = blockIdx.x * 8 + warp_local;
    const int lane        = threadIdx.x & 31;

    // ---- per-lane scalar indices (shared by all 4 rows) ------------------
    int h_i = 4 * lane + 1;
    if (lane == 0) h_i = 1;
    if (lane == 1) h_i = 6;

    int t_i = 3717 + 4 * lane;
    if (lane == 29) t_i = 3721;                   // duplicate 3721
    if (lane == 30) t_i = 3839;
    if (lane == 31) t_i = 3841;

    const int k     = lane >> 1;
    const int comp  = lane & 1;
    const int p1    = 16 + k;
    const bool act1 = (p1 < 28);
    const int m0_i  = 124 * k + 245 + 4 * comp;
    const int m1_i  = 124 * (act1 ? p1 : 27) + 245 + 4 * comp;

    // 4 CONSECUTIVE rows per warp (61 KB window).
    const float* __restrict__ r0 = maze + (size_t)(4 * warp_global) * MAZE_LEN;
    const float* __restrict__ r1 = r0 + MAZE_LEN;
    const float* __restrict__ r2 = r1 + MAZE_LEN;
    const float* __restrict__ r3 = r2 + MAZE_LEN;

    // ---- front-batch all 16 scalar loads (LDG.E.NC) ----------------------
    const float h0 = __ldg(r0 + h_i), t0 = __ldg(r0 + t_i);
    const float a0 = __ldg(r0 + m0_i), b0l = __ldg(r0 + m1_i);
    const float h1 = __ldg(r1 + h_i), t1 = __ldg(r1 + t_i);
    const float a1 = __ldg(r1 + m0_i), b1l = __ldg(r1 + m1_i);
    const float h2 = __ldg(r2 + h_i), t2 = __ldg(r2 + t_i);
    const float a2 = __ldg(r2 + m0_i), b2l = __ldg(r2 + m1_i);
    const float h3 = __ldg(r3 + h_i), t3 = __ldg(r3 + t_i);
    const float a3 = __ldg(r3 + m0_i), b3l = __ldg(r3 + m1_i);

    const float b0 = act1 ? b0l : 1.0f;           // dummy -> rcp(1)=1, in constant
    const float b1 = act1 ? b1l : 1.0f;
    const float b2 = act1 ? b2l : 1.0f;
    const float b3 = act1 ? b3l : 1.0f;

    float s0 = fold4(h0, t0, a0, b0);
    float s1 = fold4(h1, t1, a1, b1);
    float s2 = fold4(h2, t2, a2, b2);
    float s3 = fold4(h3, t3, a3, b3);

    // ---- warp reduction of all 4 rows' S ---------------------------------
    #pragma unroll
    for (int off = 16; off > 0; off >>= 1) {
        s0 += __shfl_xor_sync(0xffffffffu, s0, off);
        s1 += __shfl_xor_sync(0xffffffffu, s1, off);
        s2 += __shfl_xor_sync(0xffffffffu, s2, off);
        s3 += __shfl_xor_sync(0xffffffffu, s3, off);
    }

    __shared__ float warp_vals[8];
    if (lane == 0) {
        // x==0 -> inf -> fminf -> 90; two zeros -> NaN -> fminf -> 90 (matches clip).
        const float v0 = fminf(logf(s0 - 127.0f), 90.0f);
        const float v1 = fminf(logf(s1 - 127.0f), 90.0f);
        const float v2 = fminf(logf(s2 - 127.0f), 90.0f);
        const float v3 = fminf(logf(s3 - 127.0f), 90.0f);
        warp_vals[warp_local] = (v0 + v1) + (v2 + v3);
    }
    __syncthreads();

    if (threadIdx.x == 0) {
        float t = 0.0f;
        #pragma unroll
        for (int i = 0; i < 8; i++) t += warp_vals[i];
        atomicAdd(out, t * (1.0f / (float)BATCH));   // exact power-of-two scale
    }
}

extern "C" void kernel_launch(void* const* d_in, const int* in_sizes, int n_in,
                              void* d_out, int out_size)
{
    const float* maze = (const float*)d_in[0];
    float*       out  = (float*)d_out;

    cudaMemsetAsync(out, 0, sizeof(float), 0);

    const int blocks = NWARPS / 8;                  // 512 CTAs, 256 threads each
    fuzzy_chain_kernel<<<blocks, 256>>>(maze, out);
}